// round 14
// baseline (speedup 1.0000x reference)
#include <cuda_runtime.h>
#include <cstdint>

// TemporalGCN — 2 (b,t) per block, 256 threads. Single-pass TF32 mma
// (m16n8k8), W pre-converted + packed in fragment order. Mixes fp32.
// R13: fix sX row stride 100 -> 196 words (tf32 row = 192 words, not 48).

#define NBLK 8192
#define SXS  196             // sX row stride, words (768B data, conflict-free frags)
#define NWT0 (24*4*4*2*32)   // 24576 packed W0 fragments
#define NWT1 (16*4*4*2*32)   // 16384 packed W1 fragments
__device__ uint32_t g_tw0[NWT0], g_tw1[NWT1];

__device__ __forceinline__ uint32_t tf32_bits(float v) {
    uint32_t u;
    asm("cvt.rna.tf32.f32 %0, %1;" : "=r"(u) : "f"(v));
    return u;
}
__device__ __forceinline__ void mma_tf32(float* c, const uint32_t* a, const uint32_t* b) {
    asm volatile("mma.sync.aligned.m16n8k8.row.col.f32.tf32.tf32.f32 "
        "{%0,%1,%2,%3}, {%4,%5,%6,%7}, {%8,%9}, {%0,%1,%2,%3};"
        : "+f"(c[0]), "+f"(c[1]), "+f"(c[2]), "+f"(c[3])
        : "r"(a[0]), "r"(a[1]), "r"(a[2]), "r"(a[3]), "r"(b[0]), "r"(b[1]));
}

// pack W into tf32 fragment order: slot (((ks*4+w)*4+tt)*2+r)*32 + lane
// holds W[n = w*32+tt*8+(l>>2)][k = ks*8+(l&3)+r*4]
__global__ __launch_bounds__(256) void prep_kernel(const float* __restrict__ W0,
                                                   const float* __restrict__ W1) {
    int i = blockIdx.x * 256 + threadIdx.x;
    if (i < NWT0) {
        int l = i & 31, r = (i >> 5) & 1, tt = (i >> 6) & 3, w = (i >> 8) & 3, ks = i >> 10;
        int n = w*32 + tt*8 + (l >> 2);
        int k = ks*8 + (l & 3) + r*4;
        g_tw0[i] = tf32_bits(W0[n*192 + k]);
    } else if (i < NWT0 + NWT1) {
        int j = i - NWT0;
        int l = j & 31, r = (j >> 5) & 1, tt = (j >> 6) & 3, w = (j >> 8) & 3, ks = j >> 10;
        int n = w*32 + tt*8 + (l >> 2);
        int k = ks*8 + (l & 3) + r*4;
        g_tw1[j] = tf32_bits(W1[n*128 + k]);
    }
}

// smem: sX 48*196*4 = 37632 (tf32 bits)
//       sY 48*128*4 = 24576 fp32 (ALIASES sX, dead after phase A)
//       sY2 48*132*4 = 25344 (tf32 bits, stride 132)
//       sA 2*528*4 = 4224 | sRed 512*4 = 2048
#define OFF_SX   0
#define OFF_SY   0
#define OFF_SY2  37632
#define OFF_SA   62976
#define OFF_RED  67200
#define SMEM_BYTES 69248     // 3 blocks/SM (207.7KB/SM)

__global__ __launch_bounds__(256, 3) void fused_kernel(
    const float* __restrict__ x,  const float* __restrict__ A,
    const float* __restrict__ b0, const float* __restrict__ b1,
    float* __restrict__ out)
{
    extern __shared__ char sm[];
    uint32_t* sXu  = reinterpret_cast<uint32_t*>(sm + OFF_SX);
    float*    sY   = reinterpret_cast<float*>(sm + OFF_SY);
    uint32_t* sY2u = reinterpret_cast<uint32_t*>(sm + OFF_SY2);
    float*    sA   = reinterpret_cast<float*>(sm + OFF_SA);
    float*    sRed = reinterpret_cast<float*>(sm + OFF_RED);

    const int bt0 = blockIdx.x * 2;
    const int t = threadIdx.x;
    const int wid = t >> 5, l = t & 31;
    const int gr = l >> 2, gc = l & 3;
    // GEMM: warp owns 16 N-cols
    const int n0 = wid * 16;
    const int wq = wid >> 1;
    const int wr = (wid & 1) * 2;
    // Mix: (btl, chalf, h columns)
    const int btl   = wid >> 2;
    const int chalf = (wid >> 1) & 1;
    const int h0 = ((wid & 1) << 5) + l, h1 = h0 + 64;
    const int cbase = chalf * 11;

    // ---- Stage: x -> tf32 bits rows 0-21,24-45 (stride SXS); A -> sA ----
    {
        const float* xr = x + (size_t)bt0 * (22*192);
        for (int i = t; i < 44*48; i += 256) {          // 48 float4 per row
            int row = i / 48, cr = i - row*48;
            int srow = (row < 22) ? row : row + 2;
            float4 v = reinterpret_cast<const float4*>(xr + row*192)[cr];
            *reinterpret_cast<uint4*>(sXu + srow*SXS + cr*4) =
                make_uint4(tf32_bits(v.x), tf32_bits(v.y), tf32_bits(v.z), tf32_bits(v.w));
        }
        const float* Ag = A + (size_t)bt0 * 484;
        for (int i = t; i < 968; i += 256) {
            int b_ = i / 484, rem = i - b_*484;
            int c = rem / 22, j = rem - c*22;
            sA[b_*528 + c*24 + j] = Ag[i];
        }
        if (t < 88) {
            int b_ = t / 44, rr = (t % 44) >> 1;
            sA[b_*528 + rr*24 + 22 + (t & 1)] = 0.f;
        }
    }
    __syncthreads();

    float acc[3][2][4];

    // ==== Phase A: y = x @ W0^T  (M=48, K=192, 24 k8-steps) ====
    #pragma unroll
    for (int mi = 0; mi < 3; mi++)
        #pragma unroll
        for (int tt = 0; tt < 2; tt++)
            #pragma unroll
            for (int q = 0; q < 4; q++) acc[mi][tt][q] = 0.f;

    #pragma unroll 4
    for (int ks = 0; ks < 24; ks++) {
        uint32_t af[3][4], bf[2][2];
        #pragma unroll
        for (int mi = 0; mi < 3; mi++) {
            int r0 = (mi*16 + gr)*SXS + ks*8 + gc;
            af[mi][0] = sXu[r0];
            af[mi][1] = sXu[r0 + 8*SXS];
            af[mi][2] = sXu[r0 + 4];
            af[mi][3] = sXu[r0 + 8*SXS + 4];
        }
        const uint32_t* pB = g_tw0 + ((ks*4 + wq)*4 + wr)*64 + l;
        bf[0][0] = pB[0];   bf[0][1] = pB[32];
        bf[1][0] = pB[64];  bf[1][1] = pB[96];
        #pragma unroll
        for (int mi = 0; mi < 3; mi++)
            #pragma unroll
            for (int tt = 0; tt < 2; tt++) mma_tf32(acc[mi][tt], af[mi], bf[tt]);
    }
    __syncthreads();    // all sX reads complete before sY overwrites region

    #pragma unroll
    for (int mi = 0; mi < 3; mi++)
        #pragma unroll
        for (int tt = 0; tt < 2; tt++) {
            int r0 = mi*16 + gr, c = n0 + tt*8 + gc*2;
            if (r0 < 22 || (r0 >= 24 && r0 < 46))
                *reinterpret_cast<float2*>(sY + r0*128 + c) =
                    make_float2(acc[mi][tt][0], acc[mi][tt][1]);
            int r1 = r0 + 8;
            if (r1 < 22 || (r1 >= 24 && r1 < 46))
                *reinterpret_cast<float2*>(sY + r1*128 + c) =
                    make_float2(acc[mi][tt][2], acc[mi][tt][3]);
        }
    sY[22*128 + t] = 0.f;      // zero pad rows 22,23 then 46,47
    sY[46*128 + t] = 0.f;
    __syncthreads();

    // ==== Phase B: y2 = relu(b0 + A@y) -> tf32 bits (one btl per warp) ====
    {
        const float bb0 = b0[h0], bb1 = b0[h1];
        const float* sYb = sY + btl*24*128;
        const float4* sA4 = reinterpret_cast<const float4*>(sA + btl*528);
        float a0[11], a1[11];
        #pragma unroll
        for (int c = 0; c < 11; c++) { a0[c] = bb0; a1[c] = bb1; }
        #pragma unroll
        for (int jg = 0; jg < 6; jg++) {
            float yv0[4], yv1[4];
            #pragma unroll
            for (int q = 0; q < 4; q++) {
                yv0[q] = sYb[(jg*4+q)*128 + h0];
                yv1[q] = sYb[(jg*4+q)*128 + h1];
            }
            #pragma unroll
            for (int c = 0; c < 11; c++) {
                float4 av = sA4[(cbase + c)*6 + jg];
                a0[c] += av.x*yv0[0] + av.y*yv0[1] + av.z*yv0[2] + av.w*yv0[3];
                a1[c] += av.x*yv1[0] + av.y*yv1[1] + av.z*yv1[2] + av.w*yv1[3];
            }
        }
        #pragma unroll
        for (int c = 0; c < 11; c++) {
            int row = btl*24 + cbase + c;
            sY2u[row*132 + h0] = tf32_bits(fmaxf(a0[c], 0.f));
            sY2u[row*132 + h1] = tf32_bits(fmaxf(a1[c], 0.f));
        }
    }
    __syncthreads();

    // ==== Phase C: y3 = y2 @ W1^T  (M=48, K=128, 16 k8-steps) ====
    #pragma unroll
    for (int mi = 0; mi < 3; mi++)
        #pragma unroll
        for (int tt = 0; tt < 2; tt++)
            #pragma unroll
            for (int q = 0; q < 4; q++) acc[mi][tt][q] = 0.f;

    #pragma unroll 4
    for (int ks = 0; ks < 16; ks++) {
        uint32_t af[3][4], bf[2][2];
        #pragma unroll
        for (int mi = 0; mi < 3; mi++) {
            int r0 = (mi*16 + gr)*132 + ks*8 + gc;
            af[mi][0] = sY2u[r0];
            af[mi][1] = sY2u[r0 + 1056];   // +8 rows
            af[mi][2] = sY2u[r0 + 4];
            af[mi][3] = sY2u[r0 + 1060];
        }
        const uint32_t* pB = g_tw1 + ((ks*4 + wq)*4 + wr)*64 + l;
        bf[0][0] = pB[0];   bf[0][1] = pB[32];
        bf[1][0] = pB[64];  bf[1][1] = pB[96];
        #pragma unroll
        for (int mi = 0; mi < 3; mi++)
            #pragma unroll
            for (int tt = 0; tt < 2; tt++) mma_tf32(acc[mi][tt], af[mi], bf[tt]);
    }
    // sY (sX region) dead since phase B completed; write epilogue directly
    #pragma unroll
    for (int mi = 0; mi < 3; mi++)
        #pragma unroll
        for (int tt = 0; tt < 2; tt++) {
            int r0 = mi*16 + gr, c = n0 + tt*8 + gc*2;
            if (r0 < 22 || (r0 >= 24 && r0 < 46))
                *reinterpret_cast<float2*>(sY + r0*128 + c) =
                    make_float2(acc[mi][tt][0], acc[mi][tt][1]);
            int r1 = r0 + 8;
            if (r1 < 22 || (r1 >= 24 && r1 < 46))
                *reinterpret_cast<float2*>(sY + r1*128 + c) =
                    make_float2(acc[mi][tt][2], acc[mi][tt][3]);
        }
    __syncthreads();

    // ==== Phase D: out = mean_c relu(b1 + A@y3) (one btl per warp) ====
    {
        const float bb0 = b1[h0], bb1 = b1[h1];
        const float* sYb = sY + btl*24*128;
        const float4* sA4 = reinterpret_cast<const float4*>(sA + btl*528);
        float a0[11], a1[11];
        #pragma unroll
        for (int c = 0; c < 11; c++) { a0[c] = bb0; a1[c] = bb1; }
        #pragma unroll
        for (int jg = 0; jg < 6; jg++) {
            float yv0[4], yv1[4];
            #pragma unroll
            for (int q = 0; q < 4; q++) {
                yv0[q] = sYb[(jg*4+q)*128 + h0];
                yv1[q] = sYb[(jg*4+q)*128 + h1];
            }
            #pragma unroll
            for (int c = 0; c < 11; c++) {
                float4 av = sA4[(cbase + c)*6 + jg];
                a0[c] += av.x*yv0[0] + av.y*yv0[1] + av.z*yv0[2] + av.w*yv0[3];
                a1[c] += av.x*yv1[0] + av.y*yv1[1] + av.z*yv1[2] + av.w*yv1[3];
            }
        }
        float p0 = 0.f, p1 = 0.f;
        #pragma unroll
        for (int c = 0; c < 11; c++) { p0 += fmaxf(a0[c], 0.f); p1 += fmaxf(a1[c], 0.f); }
        sRed[btl*256 + chalf*128 + h0] = p0;
        sRed[btl*256 + chalf*128 + h1] = p1;
        __syncthreads();
        int ob = t >> 7, oh = t & 127;
        out[(size_t)(bt0 + ob)*128 + oh] =
            (sRed[ob*256 + oh] + sRed[ob*256 + 128 + oh]) * (1.f/22.f);
    }
}

extern "C" void kernel_launch(void* const* d_in, const int* in_sizes, int n_in,
                              void* d_out, int out_size) {
    const float* x  = (const float*)d_in[0];   // [32,512,22,192]
    const float* A  = (const float*)d_in[1];   // [16384,22,22]
    const float* W0 = (const float*)d_in[2];   // [128,192]
    const float* b0 = (const float*)d_in[3];
    const float* W1 = (const float*)d_in[4];   // [128,128]
    const float* b1 = (const float*)d_in[5];
    float* out = (float*)d_out;                // [16384,128]

    cudaFuncSetAttribute(fused_kernel, cudaFuncAttributeMaxDynamicSharedMemorySize, SMEM_BYTES);
    prep_kernel<<<(NWT0 + NWT1 + 255) / 256, 256>>>(W0, W1);
    fused_kernel<<<NBLK, 256, SMEM_BYTES>>>(x, A, b0, b1, out);
}

// round 16
// speedup vs baseline: 1.5608x; 1.5608x over previous
#include <cuda_runtime.h>
#include <cuda_bf16.h>
#include <cstdint>

// TemporalGCN — 2 (b,t) per block, 128 threads (R10 tiling), lifetime-packed
// smem (54912B -> 4 blocks/SM) + reg cap 128. bf16x3 split mma, packed W.

#define NBLK  8192
#define Y2S   136      // bf16 elems per Y2 row (272B, ldmatrix conflict-free)

#define NW0  (12*4*4*2*32)
#define NW1  (8*4*4*2*32)
__device__ uint32_t g_pw0h[NW0], g_pw0l[NW0];
__device__ uint32_t g_pw1h[NW1], g_pw1l[NW1];

__device__ __forceinline__ uint32_t smem_u32(const void* p) {
    uint32_t a;
    asm("{ .reg .u64 t; cvta.to.shared.u64 t, %1; cvt.u32.u64 %0, t; }" : "=r"(a) : "l"(p));
    return a;
}
__device__ __forceinline__ void ldsm_x4(uint32_t* r, uint32_t addr) {
    asm volatile("ldmatrix.sync.aligned.m8n8.x4.shared.b16 {%0,%1,%2,%3}, [%4];"
        : "=r"(r[0]), "=r"(r[1]), "=r"(r[2]), "=r"(r[3]) : "r"(addr));
}
__device__ __forceinline__ void mma_bf16(float* c, const uint32_t* a, const uint32_t* b) {
    asm volatile("mma.sync.aligned.m16n8k16.row.col.f32.bf16.bf16.f32 "
        "{%0,%1,%2,%3}, {%4,%5,%6,%7}, {%8,%9}, {%0,%1,%2,%3};"
        : "+f"(c[0]), "+f"(c[1]), "+f"(c[2]), "+f"(c[3])
        : "r"(a[0]), "r"(a[1]), "r"(a[2]), "r"(a[3]), "r"(b[0]), "r"(b[1]));
}
__device__ __forceinline__ void split2(float v0, float v1, uint32_t& hw, uint32_t& lw) {
    __nv_bfloat16 h0 = __float2bfloat16(v0), h1 = __float2bfloat16(v1);
    __nv_bfloat16 l0 = __float2bfloat16(v0 - __bfloat162float(h0));
    __nv_bfloat16 l1 = __float2bfloat16(v1 - __bfloat162float(h1));
    hw = (uint32_t)__bfloat16_as_ushort(h0) | ((uint32_t)__bfloat16_as_ushort(h1) << 16);
    lw = (uint32_t)__bfloat16_as_ushort(l0) | ((uint32_t)__bfloat16_as_ushort(l1) << 16);
}

__global__ __launch_bounds__(256) void prep_kernel(const float* __restrict__ W0,
                                                   const float* __restrict__ W1) {
    int i = blockIdx.x * 256 + threadIdx.x;
    if (i < NW0) {
        int l = i & 31, r = (i >> 5) & 1, tt = (i >> 6) & 3, w = (i >> 8) & 3, ks = i >> 10;
        int nr = w*32 + tt*8 + (l >> 2);
        int k  = ks*16 + (l & 3)*2 + r*8;
        split2(W0[nr*192 + k], W0[nr*192 + k + 1], g_pw0h[i], g_pw0l[i]);
    } else if (i < NW0 + NW1) {
        int j = i - NW0;
        int l = j & 31, r = (j >> 5) & 1, tt = (j >> 6) & 3, w = (j >> 8) & 3, ks = j >> 10;
        int nr = w*32 + tt*8 + (l >> 2);
        int k  = ks*16 + (l & 3)*2 + r*8;
        split2(W1[nr*128 + k], W1[nr*128 + k + 1], g_pw1h[j], g_pw1l[j]);
    }
}

// Lifetime-packed smem (bytes):
//   [0,19200)      XH (stage+phase A)      -> then sY (y/y3) spans [0,24576)
//   [19200,38400)  XL (stage+phase A)
//   [24576,37632)  Y2H (phase B write, C read)   — inside dead XL
//   [37632,50688)  Y2L (phase B write, C read)   — sRed reuses [37632,39680) in D
//   [50688,54912)  sA
#define OFF_XH   0
#define OFF_XL   19200
#define OFF_Y2H  24576
#define OFF_Y2L  37632
#define OFF_SA   50688
#define OFF_RED  37632
#define SMEM_BYTES 54912      // 4 blocks/SM (219.6KB)

__global__ __launch_bounds__(128, 4) void fused_kernel(
    const float* __restrict__ x,  const float* __restrict__ A,
    const float* __restrict__ b0, const float* __restrict__ b1,
    float* __restrict__ out)
{
    extern __shared__ char sm[];
    float* sY   = reinterpret_cast<float*>(sm + OFF_XH);    // aliases XH/XL head
    float* sA   = reinterpret_cast<float*>(sm + OFF_SA);
    float* sRed = reinterpret_cast<float*>(sm + OFF_RED);   // aliases Y2L (dead after C)
    const uint32_t sbase = smem_u32(sm);

    const int bt0 = blockIdx.x * 2;
    const int t = threadIdx.x;
    const int wid = t >> 5, l = t & 31;
    const int n0 = wid * 32;
    const int h0 = ((wid & 1) << 5) + l, h1 = h0 + 64;
    const int chalf = wid >> 1, cbase = chalf * 11;

    // ---- Stage: 44 contiguous x rows -> bf16 hi/lo (rows 0-21, 24-45); A ----
    {
        const float* xr = x + (size_t)bt0 * (22*192);
        for (int i = t; i < 44*24; i += 128) {
            int row = i / 24, cr = i - row * 24;
            int srow = (row < 22) ? row : row + 2;
            const float4* g4 = reinterpret_cast<const float4*>(xr + row*192 + cr*8);
            float4 a = g4[0], b = g4[1];
            uint32_t hw[4], lw[4];
            split2(a.x, a.y, hw[0], lw[0]); split2(a.z, a.w, hw[1], lw[1]);
            split2(b.x, b.y, hw[2], lw[2]); split2(b.z, b.w, hw[3], lw[3]);
            *reinterpret_cast<uint4*>(sm + OFF_XH + srow*400 + cr*16) =
                make_uint4(hw[0], hw[1], hw[2], hw[3]);
            *reinterpret_cast<uint4*>(sm + OFF_XL + srow*400 + cr*16) =
                make_uint4(lw[0], lw[1], lw[2], lw[3]);
        }
        const float* Ag = A + (size_t)bt0 * 484;
        for (int i = t; i < 968; i += 128) {
            int b_ = i / 484, rem = i - b_*484;
            int c = rem / 22, j = rem - c*22;
            sA[b_*528 + c*24 + j] = Ag[i];
        }
        if (t < 88) {
            int b_ = t / 44, rr = (t % 44) >> 1;
            sA[b_*528 + rr*24 + 22 + (t & 1)] = 0.f;
        }
    }
    __syncthreads();

    float acc[3][4][4];
    const int aoff  = (l & 15) * 400 + (l >> 4) * 16;
    const int aoff2 = (l & 15) * 272 + (l >> 4) * 16;

    // ==== Phase A: y = x @ W0^T  (M=48 tile, K=192) ====
    #pragma unroll
    for (int mi = 0; mi < 3; mi++)
        #pragma unroll
        for (int tt = 0; tt < 4; tt++)
            #pragma unroll
            for (int q = 0; q < 4; q++) acc[mi][tt][q] = 0.f;

    for (int ks = 0; ks < 12; ks++) {
        uint32_t ah[3][4], al[3][4], bh[4][2], bl[4][2];
        #pragma unroll
        for (int mi = 0; mi < 3; mi++) {
            ldsm_x4(ah[mi], sbase + OFF_XH + mi*16*400 + ks*32 + aoff);
            ldsm_x4(al[mi], sbase + OFF_XL + mi*16*400 + ks*32 + aoff);
        }
        const uint32_t* pH = g_pw0h + ((ks*4 + wid)*4)*64 + l;
        const uint32_t* pL = g_pw0l + ((ks*4 + wid)*4)*64 + l;
        #pragma unroll
        for (int tt = 0; tt < 4; tt++) {
            bh[tt][0] = pH[tt*64];  bh[tt][1] = pH[tt*64 + 32];
            bl[tt][0] = pL[tt*64];  bl[tt][1] = pL[tt*64 + 32];
        }
        #pragma unroll
        for (int mi = 0; mi < 3; mi++)
            #pragma unroll
            for (int tt = 0; tt < 4; tt++) mma_bf16(acc[mi][tt], ah[mi], bh[tt]);
        #pragma unroll
        for (int mi = 0; mi < 3; mi++)
            #pragma unroll
            for (int tt = 0; tt < 4; tt++) mma_bf16(acc[mi][tt], al[mi], bh[tt]);
        #pragma unroll
        for (int mi = 0; mi < 3; mi++)
            #pragma unroll
            for (int tt = 0; tt < 4; tt++) mma_bf16(acc[mi][tt], ah[mi], bl[tt]);
    }
    __syncthreads();    // all XH/XL ldsm complete before sY overwrites

    #pragma unroll
    for (int mi = 0; mi < 3; mi++)
        #pragma unroll
        for (int tt = 0; tt < 4; tt++) {
            int r0 = mi*16 + (l >> 2), c = n0 + tt*8 + (l & 3)*2;
            if (r0 < 22 || (r0 >= 24 && r0 < 46))
                *reinterpret_cast<float2*>(sY + r0*128 + c) =
                    make_float2(acc[mi][tt][0], acc[mi][tt][1]);
            int r1 = r0 + 8;
            if (r1 < 22 || (r1 >= 24 && r1 < 46))
                *reinterpret_cast<float2*>(sY + r1*128 + c) =
                    make_float2(acc[mi][tt][2], acc[mi][tt][3]);
        }
    {   // zero pad rows 22,23,46,47
        sY[22*128 + t] = 0.f;  sY[23*128 + t] = 0.f;
        sY[46*128 + t] = 0.f;  sY[47*128 + t] = 0.f;
    }
    __syncthreads();

    // ==== Phase B: y2 = relu(b0 + A@y) -> bf16 hi/lo (both bt) ====
    {
        const float bb0 = b0[h0], bb1 = b0[h1];
        __nv_bfloat16* y2h = reinterpret_cast<__nv_bfloat16*>(sm + OFF_Y2H);
        __nv_bfloat16* y2l = reinterpret_cast<__nv_bfloat16*>(sm + OFF_Y2L);
        #pragma unroll
        for (int btl = 0; btl < 2; btl++) {
            const float* sYb = sY + btl*24*128;
            const float4* sA4 = reinterpret_cast<const float4*>(sA + btl*528);
            float a0[11], a1[11];
            #pragma unroll
            for (int c = 0; c < 11; c++) { a0[c] = bb0; a1[c] = bb1; }
            #pragma unroll
            for (int jg = 0; jg < 6; jg++) {
                float yv0[4], yv1[4];
                #pragma unroll
                for (int q = 0; q < 4; q++) {
                    yv0[q] = sYb[(jg*4+q)*128 + h0];
                    yv1[q] = sYb[(jg*4+q)*128 + h1];
                }
                #pragma unroll
                for (int c = 0; c < 11; c++) {
                    float4 av = sA4[(cbase + c)*6 + jg];
                    a0[c] += av.x*yv0[0] + av.y*yv0[1] + av.z*yv0[2] + av.w*yv0[3];
                    a1[c] += av.x*yv1[0] + av.y*yv1[1] + av.z*yv1[2] + av.w*yv1[3];
                }
            }
            #pragma unroll
            for (int c = 0; c < 11; c++) {
                int row = btl*24 + cbase + c;
                float v0 = fmaxf(a0[c], 0.f), v1 = fmaxf(a1[c], 0.f);
                __nv_bfloat16 hh0 = __float2bfloat16(v0), hh1 = __float2bfloat16(v1);
                y2h[row*Y2S + h0] = hh0;
                y2l[row*Y2S + h0] = __float2bfloat16(v0 - __bfloat162float(hh0));
                y2h[row*Y2S + h1] = hh1;
                y2l[row*Y2S + h1] = __float2bfloat16(v1 - __bfloat162float(hh1));
            }
        }
    }
    __syncthreads();

    // ==== Phase C: y3 = y2 @ W1^T  (M=48 tile, K=128) ====
    #pragma unroll
    for (int mi = 0; mi < 3; mi++)
        #pragma unroll
        for (int tt = 0; tt < 4; tt++)
            #pragma unroll
            for (int q = 0; q < 4; q++) acc[mi][tt][q] = 0.f;

    for (int ks = 0; ks < 8; ks++) {
        uint32_t ah[3][4], al[3][4], bh[4][2], bl[4][2];
        #pragma unroll
        for (int mi = 0; mi < 3; mi++) {
            ldsm_x4(ah[mi], sbase + OFF_Y2H + mi*16*272 + ks*32 + aoff2);
            ldsm_x4(al[mi], sbase + OFF_Y2L + mi*16*272 + ks*32 + aoff2);
        }
        const uint32_t* pH = g_pw1h + ((ks*4 + wid)*4)*64 + l;
        const uint32_t* pL = g_pw1l + ((ks*4 + wid)*4)*64 + l;
        #pragma unroll
        for (int tt = 0; tt < 4; tt++) {
            bh[tt][0] = pH[tt*64];  bh[tt][1] = pH[tt*64 + 32];
            bl[tt][0] = pL[tt*64];  bl[tt][1] = pL[tt*64 + 32];
        }
        #pragma unroll
        for (int mi = 0; mi < 3; mi++)
            #pragma unroll
            for (int tt = 0; tt < 4; tt++) mma_bf16(acc[mi][tt], ah[mi], bh[tt]);
        #pragma unroll
        for (int mi = 0; mi < 3; mi++)
            #pragma unroll
            for (int tt = 0; tt < 4; tt++) mma_bf16(acc[mi][tt], al[mi], bh[tt]);
        #pragma unroll
        for (int mi = 0; mi < 3; mi++)
            #pragma unroll
            for (int tt = 0; tt < 4; tt++) mma_bf16(acc[mi][tt], ah[mi], bl[tt]);
    }
    // y3 -> sY [0,24576): disjoint from Y2H/Y2L still being read by other warps
    #pragma unroll
    for (int mi = 0; mi < 3; mi++)
        #pragma unroll
        for (int tt = 0; tt < 4; tt++) {
            int r0 = mi*16 + (l >> 2), c = n0 + tt*8 + (l & 3)*2;
            if (r0 < 22 || (r0 >= 24 && r0 < 46))
                *reinterpret_cast<float2*>(sY + r0*128 + c) =
                    make_float2(acc[mi][tt][0], acc[mi][tt][1]);
            int r1 = r0 + 8;
            if (r1 < 22 || (r1 >= 24 && r1 < 46))
                *reinterpret_cast<float2*>(sY + r1*128 + c) =
                    make_float2(acc[mi][tt][2], acc[mi][tt][3]);
        }
    __syncthreads();

    // ==== Phase D: out = mean_c relu(b1 + A@y3) (both bt) ====
    {
        const float bb0 = b1[h0], bb1 = b1[h1];
        #pragma unroll
        for (int btl = 0; btl < 2; btl++) {
            const float* sYb = sY + btl*24*128;
            const float4* sA4 = reinterpret_cast<const float4*>(sA + btl*528);
            float a0[11], a1[11];
            #pragma unroll
            for (int c = 0; c < 11; c++) { a0[c] = bb0; a1[c] = bb1; }
            #pragma unroll
            for (int jg = 0; jg < 6; jg++) {
                float yv0[4], yv1[4];
                #pragma unroll
                for (int q = 0; q < 4; q++) {
                    yv0[q] = sYb[(jg*4+q)*128 + h0];
                    yv1[q] = sYb[(jg*4+q)*128 + h1];
                }
                #pragma unroll
                for (int c = 0; c < 11; c++) {
                    float4 av = sA4[(cbase + c)*6 + jg];
                    a0[c] += av.x*yv0[0] + av.y*yv0[1] + av.z*yv0[2] + av.w*yv0[3];
                    a1[c] += av.x*yv1[0] + av.y*yv1[1] + av.z*yv1[2] + av.w*yv1[3];
                }
            }
            float p0 = 0.f, p1 = 0.f;
            #pragma unroll
            for (int c = 0; c < 11; c++) { p0 += fmaxf(a0[c], 0.f); p1 += fmaxf(a1[c], 0.f); }
            sRed[btl*256 + chalf*128 + h0] = p0;
            sRed[btl*256 + chalf*128 + h1] = p1;
        }
        __syncthreads();
        out[(size_t)bt0*128 + t]     = (sRed[t]       + sRed[128 + t]) * (1.f/22.f);
        out[(size_t)(bt0+1)*128 + t] = (sRed[256 + t] + sRed[384 + t]) * (1.f/22.f);
    }
}

extern "C" void kernel_launch(void* const* d_in, const int* in_sizes, int n_in,
                              void* d_out, int out_size) {
    const float* x  = (const float*)d_in[0];   // [32,512,22,192]
    const float* A  = (const float*)d_in[1];   // [16384,22,22]
    const float* W0 = (const float*)d_in[2];   // [128,192]
    const float* b0 = (const float*)d_in[3];
    const float* W1 = (const float*)d_in[4];   // [128,128]
    const float* b1 = (const float*)d_in[5];
    float* out = (float*)d_out;                // [16384,128]

    cudaFuncSetAttribute(fused_kernel, cudaFuncAttributeMaxDynamicSharedMemorySize, SMEM_BYTES);
    prep_kernel<<<(NW0 + NW1 + 255) / 256, 256>>>(W0, W1);
    fused_kernel<<<NBLK, 128, SMEM_BYTES>>>(x, A, b0, b1, out);
}